// round 9
// baseline (speedup 1.0000x reference)
#include <cuda_runtime.h>

#define NQ 4
#define NL 8

typedef unsigned long long u64;

// ---------- packed f32x2 helpers ----------
__device__ __forceinline__ u64 pk2(float lo, float hi) {
    u64 r; asm("mov.b64 %0, {%1,%2};" : "=l"(r) : "f"(lo), "f"(hi)); return r;
}
__device__ __forceinline__ u64 bc2(float v) { return pk2(v, v); }
__device__ __forceinline__ u64 fma2(u64 a, u64 b, u64 c) {
    u64 d; asm("fma.rn.f32x2 %0, %1, %2, %3;" : "=l"(d) : "l"(a), "l"(b), "l"(c)); return d;
}
__device__ __forceinline__ u64 mul2(u64 a, u64 b) {
    u64 d; asm("mul.rn.f32x2 %0, %1, %2;" : "=l"(d) : "l"(a), "l"(b)); return d;
}
__device__ __forceinline__ u64 swp2(u64 v) {
    float a, b; asm("mov.b64 {%0,%1}, %2;" : "=f"(a), "=f"(b) : "l"(v)); return pk2(b, a);
}
__device__ __forceinline__ void unpk2(u64 v, float& a, float& b) {
    asm("mov.b64 {%0,%1}, %2;" : "=f"(a), "=f"(b) : "l"(v));
}
__device__ __forceinline__ float2 cmulf(float2 a, float2 b) {
    return make_float2(a.x * b.x - a.y * b.y, a.x * b.y + a.y * b.x);
}

// Fused SU(2) gate on qubit q<3 (m-space stride km = 4>>q).
// Gate G = [[g00, -conj(g10)],[g10, conj(g00)]]; 7 broadcast packs.
__device__ __forceinline__ void apply_g_k(u64 VR[8], u64 VI[8],
                                          u64 P00r, u64 P00i, u64 N00i,
                                          u64 P10r, u64 N10r, u64 P10i, u64 N10i,
                                          int km) {
#pragma unroll
    for (int mm = 0; mm < 4; mm++) {
        int m = ((mm & ~(km - 1)) << 1) | (mm & (km - 1));
        int n = m | km;
        u64 ar = VR[m], ai = VI[m], br = VR[n], bi = VI[n];
        VR[m] = fma2(N10i, bi, fma2(N10r, br, fma2(N00i, ai, mul2(P00r, ar))));
        VI[m] = fma2(P10i, br, fma2(N10r, bi, fma2(P00i, ar, mul2(P00r, ai))));
        VR[n] = fma2(P00i, bi, fma2(P00r, br, fma2(N10i, ai, mul2(P10r, ar))));
        VI[n] = fma2(N00i, br, fma2(P00r, bi, fma2(P10i, ar, mul2(P10r, ai))));
    }
}

// Fused SU(2) gate on qubit 3 (lane qubit). Lane-swizzled packs:
// A={g00r,g00r} B={-g10r,g10r} C={g00i,-g00i} D={g10i,g10i} nC=-C nD=-D
__device__ __forceinline__ void apply_g_lane(u64 VR[8], u64 VI[8],
                                             u64 A, u64 B, u64 C, u64 D, u64 nC, u64 nD) {
#pragma unroll
    for (int m = 0; m < 8; m++) {
        u64 r = VR[m], i = VI[m];
        u64 rs = swp2(r), is = swp2(i);
        VR[m] = fma2(nD, is, fma2(nC, i, fma2(B, rs, mul2(A, r))));
        VI[m] = fma2(D, rs, fma2(C, r, fma2(B, is, mul2(A, i))));
    }
}

__global__ void __launch_bounds__(128)
pqc_kernel(const float* __restrict__ x, const float* __restrict__ theta,
           const float* __restrict__ lmbd, float* __restrict__ out, int B) {
    // 36 gates, SU(2): store only {u00r, u00i, u10r, u10i} per gate.
    __shared__ float4 sU4[36];
    __shared__ float sl[32];

    int t = threadIdx.x;
    if (t < 32) sl[t] = lmbd[t];

    if (t < 36) {
        int g = t;
        float t0 = theta[g * 3 + 0], t1 = theta[g * 3 + 1], t2 = theta[g * 3 + 2];
        float cx, sx, cy, sy, cz, sz;
        sincosf(0.5f * t0, &sx, &cx);
        sincosf(0.5f * t1, &sy, &cy);
        sincosf(0.5f * t2, &sz, &cz);
        // M = RY*RX (column 0 entries and row structure)
        float m00r = cy * cx, m00i = sy * sx;
        float m10r = sy * cx, m10i = -cy * sx;
        // U = RZ*M: u00 = (cz - i sz)*m00 ; u10 = (cz + i sz)*m10
        float u00r = cz * m00r + sz * m00i, u00i = cz * m00i - sz * m00r;
        float u10r = cz * m10r - sz * m10i, u10i = cz * m10i + sz * m10r;
        sU4[g] = make_float4(u00r, u00i, u10r, u10i);
    }
    __syncthreads();

    const int stride = gridDim.x * blockDim.x;
    const u64 HI_SIGN = 0x8000000000000000ULL;
    const u64 LO_SIGN = 0x0000000080000000ULL;

    // Persistent grid-stride: each thread processes 2 samples sequentially.
    // Keeps every block resident from t=0 (no wave-2 tail) at flat occupancy.
#pragma unroll 1
    for (int b = blockIdx.x * blockDim.x + t; b < B; b += stride) {
        float4 xv = reinterpret_cast<const float4*>(x)[b];
        float xa[4] = {xv.x, xv.y, xv.z, xv.w};

        // ---- init: layer-0 gates on |0000> = outer product of columns-0 (u00, u10) ----
        // amplitude index i: qubit q -> bit (3-q); lane = bit0 (qubit 3); m = i>>1
        u64 VR[8], VI[8];
        {
            float4 g0 = sU4[0], g1 = sU4[1], g2 = sU4[2], g3 = sU4[3];
            float2 c0[2] = {{g0.x, g0.y}, {g0.z, g0.w}};
            float2 c1[2] = {{g1.x, g1.y}, {g1.z, g1.w}};
            float2 c2[2] = {{g2.x, g2.y}, {g2.z, g2.w}};
            float2 c3[2] = {{g3.x, g3.y}, {g3.z, g3.w}};
            float2 t01[4], t23[4];
#pragma unroll
            for (int j = 0; j < 4; j++) {
                t01[j] = cmulf(c0[j >> 1], c1[j & 1]);
                t23[j] = cmulf(c2[j >> 1], c3[j & 1]);
            }
            u64 T23r[2], T23i[2];
#pragma unroll
            for (int b2 = 0; b2 < 2; b2++) {
                T23r[b2] = pk2(t23[b2 * 2 + 0].x, t23[b2 * 2 + 1].x);
                T23i[b2] = pk2(t23[b2 * 2 + 0].y, t23[b2 * 2 + 1].y);
            }
#pragma unroll
            for (int m = 0; m < 8; m++) {
                float2 tt = t01[m >> 1];
                int b2 = m & 1;
                u64 tr = bc2(tt.x), ti = bc2(tt.y), nti = bc2(-tt.y);
                VR[m] = fma2(nti, T23i[b2], mul2(tr, T23r[b2]));
                VI[m] = fma2(ti, T23r[b2], mul2(tr, T23i[b2]));
            }
        }

#pragma unroll 1
        for (int l = 0; l < NL; l++) {
            // CZ ring: negate amplitudes 3 (m1 hi), 6 (m3 lo), 9 (m4 hi), 12 (m6 lo)
            VR[1] ^= HI_SIGN; VI[1] ^= HI_SIGN;
            VR[3] ^= LO_SIGN; VI[3] ^= LO_SIGN;
            VR[4] ^= HI_SIGN; VI[4] ^= HI_SIGN;
            VR[6] ^= LO_SIGN; VI[6] ^= LO_SIGN;

            // Fused gates G_q = U_{l+1,q} * RX(lmbd*x) per qubit (distinct-qubit factors commute)
#pragma unroll
            for (int q = 0; q < 4; q++) {
                float4 u = sU4[(l + 1) * 4 + q];   // {u00r, u00i, u10r, u10i}
                float ang = 0.5f * sl[l * 4 + q] * xa[q];
                float s, c;
                __sincosf(ang, &s, &c);
                // G = U * RX(c, s): (u01 = -conj(u10), u11 = conj(u00))
                float g00r = u.x * c + u.w * s;    // u00r*c + u10i*s
                float g00i = u.y * c + u.z * s;    // u00i*c + u10r*s
                float g10r = u.z * c - u.y * s;    // u10r*c - u00i*s
                float g10i = u.w * c - u.x * s;    // u10i*c - u00r*s
                if (q < 3) {
                    u64 P00r = bc2(g00r), P00i = bc2(g00i), N00i = bc2(-g00i);
                    u64 P10r = bc2(g10r), N10r = bc2(-g10r);
                    u64 P10i = bc2(g10i), N10i = bc2(-g10i);
                    apply_g_k(VR, VI, P00r, P00i, N00i, P10r, N10r, P10i, N10i, 4 >> q);
                } else {
                    u64 A = bc2(g00r);
                    u64 Bp = pk2(-g10r, g10r);
                    u64 C = pk2(g00i, -g00i);
                    u64 D = bc2(g10i);
                    u64 nC = pk2(-g00i, g00i);
                    u64 nD = bc2(-g10i);
                    apply_g_lane(VR, VI, A, Bp, C, D, nC, nD);
                }
            }
        }

        // <Z0 Z1 Z2 Z3>: i=2m+lane; sign = (-1)^popc(i); lanes of a pair have opposite signs.
        float e = 0.0f;
#pragma unroll
        for (int m = 0; m < 8; m++) {
            u64 p = fma2(VI[m], VI[m], mul2(VR[m], VR[m]));
            float plo, phi;
            unpk2(p, plo, phi);
            float d = plo - phi;
            e += (__popc(m) & 1) ? -d : d;
        }
        out[b] = e;
    }
}

extern "C" void kernel_launch(void* const* d_in, const int* in_sizes, int n_in,
                              void* d_out, int out_size) {
    const float* x     = (const float*)d_in[0];   // [B, 4]
    const float* theta = (const float*)d_in[1];   // [1, 108]
    const float* lmbd  = (const float*)d_in[2];   // [32]
    float* out = (float*)d_out;                   // [B, 1]
    int B = in_sizes[0] / NQ;

    const int threads = 128;
    const int spt = 2;  // samples per thread
    int blocks = (B + threads * spt - 1) / (threads * spt);   // 1024 for B=262144
    pqc_kernel<<<blocks, threads>>>(x, theta, lmbd, out, B);
}